// round 2
// baseline (speedup 1.0000x reference)
#include <cuda_runtime.h>
#include <math.h>

// Problem constants
#define NCO   5
#define NCOIL 16
#define NPL   80            // 5*16 planes
#define NYI   384
#define OSN   768
#define PAD   192
#define PLSZ  (768*768)     // 589824 pixels per oversampled plane
#define IMGPLANE (384*384)
#define HALF_OUT ((size_t)NPL*IMGPLANE)   // 11,796,480

// Scratch (static device allocations are allowed; runtime allocation is not)
__device__ float2 g_bufA[(size_t)NPL*OSN*OSN];   // ~377 MB
__device__ float2 g_bufB[(size_t)NPL*OSN*OSN];   // ~377 MB
__device__ float2 g_twid[OSN];                   // e^{-2*pi*i*j/768}

__device__ __forceinline__ float2 cmulf(float2 a, float2 b){
    return make_float2(a.x*b.x - a.y*b.y, a.x*b.y + a.y*b.x);
}
__device__ __forceinline__ float2 caddf(float2 a, float2 b){ return make_float2(a.x+b.x, a.y+b.y); }
__device__ __forceinline__ float2 csubf(float2 a, float2 b){ return make_float2(a.x-b.x, a.y-b.y); }

__global__ void k_twid(){
    int j = blockIdx.x*blockDim.x + threadIdx.x;
    if (j < OSN){
        double a = -2.0*3.14159265358979323846*(double)j/768.0;
        g_twid[j] = make_float2((float)cos(a), (float)sin(a));
    }
}

// 768-point Stockham FFT, radices [4,4,4,4,3], NB interleaved batches.
// Data layout: element j of batch col at buf[j*NB + col].
// Returns pointer to buffer holding the result (natural order).
template<int NB, bool INV>
__device__ __forceinline__ float2* fft768(float2* s0, float2* s1, int tid, int nthr){
    float2* in  = s0;
    float2* out = s1;
    int l = 1;
    #pragma unroll
    for (int st = 0; st < 4; ++st){
        const int m = 192;              // 768/4 butterflies
        int step = 192 / l;             // 768/(4*l)
        for (int w = tid; w < m*NB; w += nthr){
            int col = w % NB;
            int idx = w / NB;
            int k = idx % l;
            int j = idx / l;
            float2 a0 = in[(idx      )*NB + col];
            float2 a1 = in[(idx +   m)*NB + col];
            float2 a2 = in[(idx + 2*m)*NB + col];
            float2 a3 = in[(idx + 3*m)*NB + col];
            float2 w1 = g_twid[k*step];
            if (INV) w1.y = -w1.y;
            float2 w2 = cmulf(w1, w1);
            float2 w3 = cmulf(w2, w1);
            a1 = cmulf(a1, w1);
            a2 = cmulf(a2, w2);
            a3 = cmulf(a3, w3);
            float2 t0 = caddf(a0, a2), t1 = csubf(a0, a2);
            float2 t2 = caddf(a1, a3), t3 = csubf(a1, a3);
            float2 b0 = caddf(t0, t2);
            float2 b2 = csubf(t0, t2);
            float2 b1, b3;
            if (!INV){ b1 = make_float2(t1.x + t3.y, t1.y - t3.x);
                       b3 = make_float2(t1.x - t3.y, t1.y + t3.x); }
            else     { b1 = make_float2(t1.x - t3.y, t1.y + t3.x);
                       b3 = make_float2(t1.x + t3.y, t1.y - t3.x); }
            int ob = j*4*l + k;
            out[(ob      )*NB + col] = b0;
            out[(ob +   l)*NB + col] = b1;
            out[(ob + 2*l)*NB + col] = b2;
            out[(ob + 3*l)*NB + col] = b3;
        }
        __syncthreads();
        float2* t = in; in = out; out = t;
        l *= 4;
    }
    // radix-3 stage: l = 256, m = 256, twiddle step = 1
    {
        const int m = 256;
        for (int w = tid; w < m*NB; w += nthr){
            int col = w % NB;
            int k   = w / NB;
            float2 a0 = in[(k      )*NB + col];
            float2 a1 = in[(k +   m)*NB + col];
            float2 a2 = in[(k + 2*m)*NB + col];
            float2 w1 = g_twid[k];
            if (INV) w1.y = -w1.y;
            float2 w2 = cmulf(w1, w1);
            a1 = cmulf(a1, w1);
            a2 = cmulf(a2, w2);
            float2 t = caddf(a1, a2);
            float2 d = csubf(a1, a2);
            float2 b0 = caddf(a0, t);
            float2 u  = make_float2(a0.x - 0.5f*t.x, a0.y - 0.5f*t.y);
            const float S = INV ? 0.86602540378443864676f : -0.86602540378443864676f;
            float2 b1 = make_float2(u.x - S*d.y, u.y + S*d.x);
            float2 b2 = make_float2(u.x + S*d.y, u.y - S*d.x);
            out[(k      )*NB + col] = b0;
            out[(k + 256)*NB + col] = b1;
            out[(k + 512)*NB + col] = b2;
        }
        __syncthreads();
    }
    return out;
}

// K1: pad + input checkerboard sign + forward row FFT (only the 384 nonzero rows)
__global__ void k_row_fwd(const float* __restrict__ re, const float* __restrict__ im){
    __shared__ float2 s0[768], s1[768];
    int p   = blockIdx.y;        // plane 0..79  (a*16 + c)
    int iy  = blockIdx.x;        // 0..383
    int tid = threadIdx.x;
    for (int x = tid; x < 768; x += blockDim.x){
        float2 v = make_float2(0.f, 0.f);
        if (x >= PAD && x < PAD + NYI){
            int ix = x - PAD;
            size_t o = ((size_t)p*NYI + iy)*NYI + ix;
            float s = ((iy + ix) & 1) ? -1.f : 1.f;   // (-1)^(y+x) (pad offsets cancel: 384 even)
            v.x = s*re[o];
            v.y = s*im[o];
        }
        s0[x] = v;
    }
    __syncthreads();
    float2* r = fft768<1,false>(s0, s1, tid, blockDim.x);
    size_t ob = ((size_t)p*OSN + (iy + PAD))*OSN;
    for (int x = tid; x < 768; x += blockDim.x) g_bufA[ob + x] = r[x];
}

// K2: forward column FFT, input pruned to the central 384 rows; writes full columns
__global__ void k_col_fwd(){
    const int NB = 4;
    __shared__ float2 s0[768*NB], s1[768*NB];
    int p  = blockIdx.y;
    int x0 = blockIdx.x * NB;
    int tid = threadIdx.x;
    for (int w = tid; w < 768*NB; w += blockDim.x){
        int col = w & 3;
        int y   = w >> 2;
        float2 v = make_float2(0.f, 0.f);
        if (y >= PAD && y < PAD + NYI)
            v = g_bufA[((size_t)p*OSN + y)*OSN + x0 + col];
        s0[y*NB + col] = v;
    }
    __syncthreads();
    float2* r = fft768<4,false>(s0, s1, tid, blockDim.x);
    for (int w = tid; w < 768*NB; w += blockDim.x){
        int col = w & 3;
        int y   = w >> 2;
        g_bufB[((size_t)p*OSN + y)*OSN + x0 + col] = r[y*NB + col];
    }
}

// K3: pointwise 5x5 complex subspace mixing across 16 coils.
// out[b,c,px] = sum_a kern[b,a,px] * in[a,c,px]; kernel tensor read exactly once.
__global__ void k_einsum(const float* __restrict__ kre, const float* __restrict__ kim){
    int px = blockIdx.x*blockDim.x + threadIdx.x;
    if (px >= PLSZ) return;
    float2 kv[25];
    #pragma unroll
    for (int q = 0; q < 25; ++q)
        kv[q] = make_float2(kre[(size_t)q*PLSZ + px], kim[(size_t)q*PLSZ + px]);
    #pragma unroll 1
    for (int c = 0; c < NCOIL; ++c){
        float2 vin[5];
        #pragma unroll
        for (int a = 0; a < 5; ++a)
            vin[a] = g_bufB[((size_t)(a*NCOIL + c))*PLSZ + px];
        #pragma unroll
        for (int b = 0; b < 5; ++b){
            float2 acc = make_float2(0.f, 0.f);
            #pragma unroll
            for (int a = 0; a < 5; ++a){
                float2 k2 = kv[b*5 + a];
                acc.x += k2.x*vin[a].x - k2.y*vin[a].y;
                acc.y += k2.x*vin[a].y + k2.y*vin[a].x;
            }
            g_bufA[((size_t)(b*NCOIL + c))*PLSZ + px] = acc;
        }
    }
}

// K4: inverse column FFT (full input), writes only the central 384 rows
__global__ void k_col_inv(){
    const int NB = 4;
    __shared__ float2 s0[768*NB], s1[768*NB];
    int p  = blockIdx.y;
    int x0 = blockIdx.x * NB;
    int tid = threadIdx.x;
    for (int w = tid; w < 768*NB; w += blockDim.x){
        int col = w & 3;
        int y   = w >> 2;
        s0[y*NB + col] = g_bufA[((size_t)p*OSN + y)*OSN + x0 + col];
    }
    __syncthreads();
    float2* r = fft768<4,true>(s0, s1, tid, blockDim.x);
    for (int w = tid; w < NYI*NB; w += blockDim.x){
        int col = w & 3;
        int y   = PAD + (w >> 2);
        g_bufB[((size_t)p*OSN + y)*OSN + x0 + col] = r[y*NB + col];
    }
}

// K5: inverse row FFT on the 384 needed rows, crop, output sign + ortho scale
__global__ void k_row_inv(float* __restrict__ out){
    __shared__ float2 s0[768], s1[768];
    int p   = blockIdx.y;
    int oy  = blockIdx.x;    // 0..383
    int tid = threadIdx.x;
    size_t ib = ((size_t)p*OSN + PAD + oy)*OSN;
    for (int x = tid; x < 768; x += blockDim.x) s0[x] = g_bufB[ib + x];
    __syncthreads();
    float2* r = fft768<1,true>(s0, s1, tid, blockDim.x);
    const float sc = 1.0f/589824.0f;   // (1/768)^2 : fwd ortho * inv ortho (inv FFT unnormalized)
    for (int ox = tid; ox < NYI; ox += blockDim.x){
        float2 v = r[PAD + ox];
        float s = ((oy + ox) & 1) ? -sc : sc;
        size_t o = ((size_t)p*NYI + oy)*NYI + ox;
        out[o]            = s*v.x;   // real part block
        out[o + HALF_OUT] = s*v.y;   // imag part block
    }
}

extern "C" void kernel_launch(void* const* d_in, const int* in_sizes, int n_in,
                              void* d_out, int out_size){
    const float* ire = (const float*)d_in[0];   // image_real [5,16,384,384]
    const float* iim = (const float*)d_in[1];   // image_imag
    const float* kre = (const float*)d_in[2];   // kern_real  [5,5,768,768]
    const float* kim = (const float*)d_in[3];   // kern_imag
    float* out = (float*)d_out;                 // [2,5,16,384,384]

    k_twid<<<3, 256>>>();

    dim3 g1(NYI, NPL);          // 384 rows x 80 planes
    k_row_fwd<<<g1, 256>>>(ire, iim);

    dim3 g2(OSN/4, NPL);        // 192 column tiles x 80 planes
    k_col_fwd<<<g2, 256>>>();

    k_einsum<<<(PLSZ + 255)/256, 256>>>(kre, kim);

    dim3 g4(OSN/4, NPL);
    k_col_inv<<<g4, 256>>>();

    dim3 g5(NYI, NPL);
    k_row_inv<<<g5, 256>>>(out);
}